// round 12
// baseline (speedup 1.0000x reference)
#include <cuda_runtime.h>
#include <cuda.h>
#include <cstdint>

// out[b,t,:] = [ features[b,t,:] @ W^T + bias , pe(positions[t]) ]
// B=16384, T=64, F=16, Dh=128. Unit = 32 rows = 32KB output.
//
// Two INDEPENDENT 128-thread half-pipelines per CTA (named barriers):
// each half owns a parity-fixed unit stream, private pe tile, private
// 2-buffer feature-half staging, private TMA store issuer.
// -> 4 desynchronized store streams per SM at the proven 32KB tile size.

#define T_DIM 64
#define F_DIM 16
#define DH    128
#define GRID  296
#define TPB   256
#define USTRIDE (GRID * 2)     // 592 unit stride per half-pipe
#define FSTG_FLOATS 4096       // 32 rows * 128 cols
#define HALF_FLOATS (3 * FSTG_FLOATS)   // fstg0, fstg1, pe
#define FFB_FLOATS  512        // 32 rows * 16
#define SMEM_BYTES  ((2 * HALF_FLOATS + 2 * 2 * FFB_FLOATS) * 4)  // 106496

__device__ __forceinline__ uint32_t smem_u32(const void* p)
{
    return (uint32_t)__cvta_generic_to_shared(p);
}
__device__ __forceinline__ void cp16(uint32_t dst, const void* src)
{
    asm volatile("cp.async.cg.shared.global [%0], [%1], 16;" :: "r"(dst), "l"(src));
}
__device__ __forceinline__ unsigned long long pack2(float a, float b)
{
    unsigned long long r;
    asm("mov.b64 %0, {%1, %2};" : "=l"(r) : "f"(a), "f"(b));
    return r;
}
__device__ __forceinline__ void fma2(unsigned long long& d,
                                     unsigned long long a, unsigned long long b)
{
    asm("fma.rn.f32x2 %0, %1, %2, %0;" : "+l"(d) : "l"(a), "l"(b));
}
__device__ __forceinline__ void half_bar(int h)
{
    asm volatile("bar.sync %0, 128;" :: "r"(h + 1) : "memory");
}

__global__ __launch_bounds__(TPB, 2) void obs_embed_kernel(
    const float* __restrict__ features,   // [B,64,16]
    const float* __restrict__ W,          // [128,16]
    const float* __restrict__ bias,       // [128]
    const int*   __restrict__ positions,  // [64]
    const __grid_constant__ CUtensorMap mapF,   // feature half (cols 0..127)
    const __grid_constant__ CUtensorMap mapP,   // pe half     (cols 128..255)
    int nUnits)                           // B*2
{
    extern __shared__ float smem[];

    const int tid  = threadIdx.x;
    const int lane = tid & 31;
    const int warp = tid >> 5;
    const int h    = warp >> 2;          // half-pipe 0 or 1
    const int wih  = warp & 3;           // warp index within half
    const bool issuer = (wih == 0 && lane == 0);

    // Per-half private regions.
    float* hbase = smem + h * HALF_FLOATS;
    float* fstg0 = hbase;                       // [32][128]
    float* fstg1 = hbase + FSTG_FLOATS;
    float* pes   = hbase + 2 * FSTG_FLOATS;     // [32][128] constant
    float* ffb   = smem + 2 * HALF_FLOATS + h * 2 * FFB_FLOATS;  // [2][32][16]

    // Half h owns units u = blockIdx*2 + h (+ USTRIDE): parity(u) = h.
    const int t0 = h * 32;
    int u = blockIdx.x * 2 + h;

    // Prologue FIRST: prefetch unit u features (2KB; warp wih owns rows
    // 8wih..8wih+7 = 512B = 32 lanes x 16B). Overlaps pe compute below.
    if (u < nUnits)
        cp16(smem_u32(ffb + wih * 128 + lane * 4),
             features + (size_t)u * 512 + wih * 128 + lane * 4);
    asm volatile("cp.async.commit_group;");

    // Constant pe tile for this half's 32 t's. All-float (proven 1.1e-6).
    for (int idx = tid & 127; idx < 32 * 64; idx += 128) {
        int r = idx >> 6, j = idx & 63;
        float pos  = (float)__ldg(positions + t0 + r);
        float invf = exp2f((float)j * (-13.287712379549449f / 32.0f));
        float s, c;
        sincosf(pos * invf, &s, &c);
        pes[r * DH + 2 * j]     = s;
        pes[r * DH + 2 * j + 1] = c;
    }

    // W into packed registers. Lane owns output cols d = 4*lane + {0..3}.
    unsigned long long wp0[16], wp1[16];
    {
        const float4* Wv = reinterpret_cast<const float4*>(W);
        #pragma unroll
        for (int q = 0; q < 4; ++q) {
            float4 w0 = __ldg(Wv + (4 * lane + 0) * 4 + q);
            float4 w1 = __ldg(Wv + (4 * lane + 1) * 4 + q);
            float4 w2 = __ldg(Wv + (4 * lane + 2) * 4 + q);
            float4 w3 = __ldg(Wv + (4 * lane + 3) * 4 + q);
            wp0[4*q+0] = pack2(w0.x, w1.x);  wp1[4*q+0] = pack2(w2.x, w3.x);
            wp0[4*q+1] = pack2(w0.y, w1.y);  wp1[4*q+1] = pack2(w2.y, w3.y);
            wp0[4*q+2] = pack2(w0.z, w1.z);  wp1[4*q+2] = pack2(w2.z, w3.z);
            wp0[4*q+3] = pack2(w0.w, w1.w);  wp1[4*q+3] = pack2(w2.w, w3.w);
        }
    }
    const unsigned long long bp0 = pack2(__ldg(bias + 4 * lane + 0),
                                         __ldg(bias + 4 * lane + 1));
    const unsigned long long bp1 = pack2(__ldg(bias + 4 * lane + 2),
                                         __ldg(bias + 4 * lane + 3));

    int p = 0;
    for (; u < nUnits; u += USTRIDE, p ^= 1) {
        // Prefetch next unit's features into the other buffer.
        {
            int un = u + USTRIDE;
            if (un < nUnits)
                cp16(smem_u32(ffb + (p ^ 1) * FFB_FLOATS + wih * 128 + lane * 4),
                     features + (size_t)un * 512 + wih * 128 + lane * 4);
            asm volatile("cp.async.commit_group;");
        }

        // Reuse gate: TMA smem-read of fstg[p] (issued 2 iters ago) done.
        // Issuer thread owns this half's bulk groups (per-thread accounting).
        if (issuer) asm volatile("cp.async.bulk.wait_group.read 1;");
        half_bar(h);

        // Current features (committed last iter / prologue) ready.
        asm volatile("cp.async.wait_group 1;");
        __syncwarp();

        float* stgp = p ? fstg1 : fstg0;
        const float* fcur = ffb + p * FFB_FLOATS + wih * 128;  // warp's 8 rows

        #pragma unroll
        for (int rr = 0; rr < 8; ++rr) {
            const float4* frow = reinterpret_cast<const float4*>(fcur + rr * 16);
            unsigned long long a0 = bp0, a1 = bp1;
            #pragma unroll
            for (int q = 0; q < 4; ++q) {
                const float4 f = frow[q];   // broadcast LDS, conflict-free
                unsigned long long ff;
                ff = pack2(f.x, f.x); fma2(a0, ff, wp0[4*q+0]); fma2(a1, ff, wp1[4*q+0]);
                ff = pack2(f.y, f.y); fma2(a0, ff, wp0[4*q+1]); fma2(a1, ff, wp1[4*q+1]);
                ff = pack2(f.z, f.z); fma2(a0, ff, wp0[4*q+2]); fma2(a1, ff, wp1[4*q+2]);
                ff = pack2(f.w, f.w); fma2(a0, ff, wp0[4*q+3]); fma2(a1, ff, wp1[4*q+3]);
            }
            uint32_t sa = smem_u32(stgp + (wih * 8 + rr) * DH + lane * 4);
            asm volatile("st.shared.v2.u64 [%0], {%1, %2};"
                         :: "r"(sa), "l"(a0), "l"(a1));
        }
        half_bar(h);

        if (issuer) {
            const int row0 = u * 32;
            asm volatile("fence.proxy.async.shared::cta;");
            asm volatile(
                "cp.async.bulk.tensor.2d.global.shared::cta.tile.bulk_group "
                "[%0, {%1, %2}], [%3];"
                :: "l"(&mapF), "r"(0), "r"(row0), "r"(smem_u32(stgp)) : "memory");
            asm volatile(
                "cp.async.bulk.tensor.2d.global.shared::cta.tile.bulk_group "
                "[%0, {%1, %2}], [%3];"
                :: "l"(&mapP), "r"(0), "r"(row0), "r"(smem_u32(pes)) : "memory");
            asm volatile("cp.async.bulk.commit_group;");
        }
    }
    // Drain outstanding bulk stores before CTA exit (smem must stay live).
    asm volatile("cp.async.bulk.wait_group 0;");
    __syncthreads();
}

extern "C" void kernel_launch(void* const* d_in, const int* in_sizes, int n_in,
                              void* d_out, int out_size)
{
    const float* features  = (const float*)d_in[0];
    const float* W         = (const float*)d_in[1];
    const float* bias      = (const float*)d_in[2];
    const int*   positions = (const int*)d_in[3];
    float* out = (float*)d_out;

    const int B = in_sizes[0] / (T_DIM * F_DIM);
    const unsigned long long nRows = (unsigned long long)B * T_DIM;

    typedef CUresult (*EncodeFn)(
        CUtensorMap*, CUtensorMapDataType, cuuint32_t, void*,
        const cuuint64_t*, const cuuint64_t*, const cuuint32_t*,
        const cuuint32_t*, CUtensorMapInterleave, CUtensorMapSwizzle,
        CUtensorMapL2promotion, CUtensorMapFloatOOBfill);
    EncodeFn encode = nullptr;
    cudaDriverEntryPointQueryResult qres;
    cudaGetDriverEntryPoint("cuTensorMapEncodeTiled", (void**)&encode,
                            cudaEnableDefault, &qres);

    // Output viewed as [nRows, 256] f32, pitch 1024B. Two column tiles:
    // cols [0,128) (feature half) and [128,256) (pe half). Box [128, 32].
    cuuint64_t dims[2]    = {128, nRows};
    cuuint64_t strides[1] = {1024};
    cuuint32_t box[2]     = {128, 32};
    cuuint32_t estr[2]    = {1, 1};

    CUtensorMap mapF, mapP;
    encode(&mapF, CU_TENSOR_MAP_DATA_TYPE_FLOAT32, 2, (void*)out,
           dims, strides, box, estr,
           CU_TENSOR_MAP_INTERLEAVE_NONE, CU_TENSOR_MAP_SWIZZLE_NONE,
           CU_TENSOR_MAP_L2_PROMOTION_L2_128B, CU_TENSOR_MAP_FLOAT_OOB_FILL_NONE);
    encode(&mapP, CU_TENSOR_MAP_DATA_TYPE_FLOAT32, 2, (void*)(out + DH),
           dims, strides, box, estr,
           CU_TENSOR_MAP_INTERLEAVE_NONE, CU_TENSOR_MAP_SWIZZLE_NONE,
           CU_TENSOR_MAP_L2_PROMOTION_L2_128B, CU_TENSOR_MAP_FLOAT_OOB_FILL_NONE);

    cudaFuncSetAttribute(obs_embed_kernel,
                         cudaFuncAttributeMaxDynamicSharedMemorySize, SMEM_BYTES);

    obs_embed_kernel<<<GRID, TPB, SMEM_BYTES>>>(features, W, bias, positions,
                                                mapF, mapP, B * 2);
}

// round 13
// speedup vs baseline: 1.0221x; 1.0221x over previous
#include <cuda_runtime.h>
#include <cstdint>

// out[b,t,:] = [ features[b,t,:] @ W^T + bias , pe(positions[t]) ]
// B=16384, T=64, F=16, Dh=128.
//
// STORE-PATH EXPERIMENT: no staging smem, no TMA. Direct STG.128 from
// registers. Warp-private 4-row units (u stride 2368 -> fixed t-block),
// pe held in 16 registers/lane, W in f32x2 registers, cp.async distance-2
// feature prefetch into 4KB warp-private smem. ZERO barriers in the loop.

#define T_DIM 64
#define F_DIM 16
#define DH    128
#define GRID  296
#define TPB   256
#define WPB   8
#define WTOT  (GRID * WPB)       // 2368, multiple of 16

__device__ __forceinline__ uint32_t smem_u32(const void* p)
{
    return (uint32_t)__cvta_generic_to_shared(p);
}
__device__ __forceinline__ void cp16(uint32_t dst, const void* src)
{
    asm volatile("cp.async.cg.shared.global [%0], [%1], 16;" :: "r"(dst), "l"(src));
}
__device__ __forceinline__ unsigned long long pack2(float a, float b)
{
    unsigned long long r;
    asm("mov.b64 %0, {%1, %2};" : "=l"(r) : "f"(a), "f"(b));
    return r;
}
__device__ __forceinline__ void fma2(unsigned long long& d,
                                     unsigned long long a, unsigned long long b)
{
    asm("fma.rn.f32x2 %0, %1, %2, %0;" : "+l"(d) : "l"(a), "l"(b));
}

__global__ __launch_bounds__(TPB, 2) void obs_embed_kernel(
    const float* __restrict__ features,   // [B,64,16]
    const float* __restrict__ W,          // [128,16]
    const float* __restrict__ bias,       // [128]
    const int*   __restrict__ positions,  // [64]
    float*       __restrict__ out,        // [B,64,256]
    int nUnits)                           // B*16 (unit = 4 rows)
{
    // Warp-private feature staging: [warp][buf][4 rows * 16 floats].
    __shared__ float ffb[WPB][2][64];

    const int lane = threadIdx.x & 31;
    const int warp = threadIdx.x >> 5;
    const int gw   = blockIdx.x * WPB + warp;
    const int t0   = (gw & 15) * 4;      // fixed t-block for this warp

    int u = gw;

    // Prologue: prefetch features for iters 0 and 1 (256B each; 16 lanes).
    #pragma unroll
    for (int i = 0; i < 2; ++i) {
        int up = u + i * WTOT;
        if (up < nUnits && lane < 16)
            cp16(smem_u32(&ffb[warp][i][lane * 4]),
                 features + (size_t)up * 64 + lane * 4);
        asm volatile("cp.async.commit_group;");
    }

    // pe in REGISTERS: for the 4 fixed t's, lane's 4 cols (pairs j0=2*lane,
    // j1=2*lane+1). All-float math, proven rel_err 1.1e-6.
    float4 pe[4];
    {
        const float c0 = -13.287712379549449f / 32.0f;
        const float if0 = exp2f((float)(2 * lane)     * c0);
        const float if1 = exp2f((float)(2 * lane + 1) * c0);
        #pragma unroll
        for (int r = 0; r < 4; ++r) {
            float pos = (float)__ldg(positions + t0 + r);
            float s0, cc0, s1, cc1;
            sincosf(pos * if0, &s0, &cc0);
            sincosf(pos * if1, &s1, &cc1);
            pe[r] = make_float4(s0, cc0, s1, cc1);
        }
    }

    // W into packed registers. Lane owns output cols d = 4*lane + {0..3}.
    unsigned long long wp0[16], wp1[16];
    {
        const float4* Wv = reinterpret_cast<const float4*>(W);
        #pragma unroll
        for (int q = 0; q < 4; ++q) {
            float4 w0 = __ldg(Wv + (4 * lane + 0) * 4 + q);
            float4 w1 = __ldg(Wv + (4 * lane + 1) * 4 + q);
            float4 w2 = __ldg(Wv + (4 * lane + 2) * 4 + q);
            float4 w3 = __ldg(Wv + (4 * lane + 3) * 4 + q);
            wp0[4*q+0] = pack2(w0.x, w1.x);  wp1[4*q+0] = pack2(w2.x, w3.x);
            wp0[4*q+1] = pack2(w0.y, w1.y);  wp1[4*q+1] = pack2(w2.y, w3.y);
            wp0[4*q+2] = pack2(w0.z, w1.z);  wp1[4*q+2] = pack2(w2.z, w3.z);
            wp0[4*q+3] = pack2(w0.w, w1.w);  wp1[4*q+3] = pack2(w2.w, w3.w);
        }
    }
    const unsigned long long bp0 = pack2(__ldg(bias + 4 * lane + 0),
                                         __ldg(bias + 4 * lane + 1));
    const unsigned long long bp1 = pack2(__ldg(bias + 4 * lane + 2),
                                         __ldg(bias + 4 * lane + 3));

    int p = 0;
    for (; u < nUnits; u += WTOT, p ^= 1) {
        // Features for u (committed 2 iters ago) ready; <=1 group may remain.
        asm volatile("cp.async.wait_group 1;");
        __syncwarp();   // cross-lane visibility of the 16 lanes' copies

        const float* fcur = &ffb[warp][p][0];

        #pragma unroll
        for (int rr = 0; rr < 4; ++rr) {
            const float4* frow = reinterpret_cast<const float4*>(fcur + rr * 16);
            unsigned long long a0 = bp0, a1 = bp1;
            #pragma unroll
            for (int q = 0; q < 4; ++q) {
                const float4 f = frow[q];   // broadcast LDS, conflict-free
                unsigned long long ff;
                ff = pack2(f.x, f.x); fma2(a0, ff, wp0[4*q+0]); fma2(a1, ff, wp1[4*q+0]);
                ff = pack2(f.y, f.y); fma2(a0, ff, wp0[4*q+1]); fma2(a1, ff, wp1[4*q+1]);
                ff = pack2(f.z, f.z); fma2(a0, ff, wp0[4*q+2]); fma2(a1, ff, wp1[4*q+2]);
                ff = pack2(f.w, f.w); fma2(a0, ff, wp0[4*q+3]); fma2(a1, ff, wp1[4*q+3]);
            }
            // Direct global stores: feature half (regs) + pe half (regs).
            float* orow = out + ((size_t)u * 4 + rr) * 256;
            asm volatile("st.global.v2.u64 [%0], {%1, %2};"
                         :: "l"(orow + lane * 4), "l"(a0), "l"(a1) : "memory");
            reinterpret_cast<float4*>(orow + DH)[lane] = pe[rr];
        }

        // Prefetch u + 2*WTOT into buffer p (its reads above are complete:
        // in-order within warp). Always commit to keep group counts aligned.
        {
            int un = u + 2 * WTOT;
            if (un < nUnits && lane < 16)
                cp16(smem_u32(&ffb[warp][p][lane * 4]),
                     features + (size_t)un * 64 + lane * 4);
            asm volatile("cp.async.commit_group;");
        }
    }
    asm volatile("cp.async.wait_group 0;");
}

extern "C" void kernel_launch(void* const* d_in, const int* in_sizes, int n_in,
                              void* d_out, int out_size)
{
    const float* features  = (const float*)d_in[0];
    const float* W         = (const float*)d_in[1];
    const float* bias      = (const float*)d_in[2];
    const int*   positions = (const int*)d_in[3];
    float* out = (float*)d_out;

    const int B = in_sizes[0] / (T_DIM * F_DIM);

    obs_embed_kernel<<<GRID, TPB>>>(features, W, bias, positions, out, B * 16);
}